// round 1
// baseline (speedup 1.0000x reference)
#include <cuda_runtime.h>
#include <math.h>

#define MAXN   500000
#define NBATCH 4096

// ---- static scratch (allocation-free rule: __device__ globals) ----
__device__ __align__(16) float g_keys[(size_t)MAXN * 128];
__device__ __align__(16) float g_k2  [(size_t)MAXN * 128];
__device__ __align__(16) float g_a   [(size_t)MAXN * 128];
__device__ __align__(16) float g_v   [(size_t)MAXN * 128];
__device__ __align__(16) float g_y   [(size_t)MAXN * 128];
__device__ int g_segstart[NBATCH + 1];

__device__ __forceinline__ float mish_f(float x) {
    float sp = (x > 20.f) ? x : log1pf(__expf(x));
    return x * tanhf(sp);
}

// ---- segment starts via binary search over sorted batch ----
__global__ void segstart_kernel(const int* __restrict__ batch, int n, int* __restrict__ segstart) {
    int b = blockIdx.x * blockDim.x + threadIdx.x;
    if (b > NBATCH) return;
    int lo = 0, hi = n;
    while (lo < hi) {
        int mid = (lo + hi) >> 1;
        if (batch[mid] < b) lo = mid + 1; else hi = mid;
    }
    segstart[b] = lo;
}

// ---- GEMM: out[n,128] = A[n,128] @ W[128,128] + bias, with fused epilogue ----
// EPI: 0 = bias only, 1 = layernorm(g,bn) + mish, 2 = (acc+bias) * mul
template <int EPI>
__global__ void __launch_bounds__(256) gemm128(
    const float* __restrict__ A, const float* __restrict__ W,
    const float* __restrict__ bias,
    const float* __restrict__ gam, const float* __restrict__ bet,
    const float* __restrict__ mul,
    float* __restrict__ out, int n)
{
    __shared__ __align__(16) float As[32][132];
    __shared__ __align__(16) float Bs[32][132];

    const int row0 = blockIdx.x * 128;
    const int tid  = threadIdx.x;
    const int ty   = tid >> 4;   // 0..15 -> row group of 8
    const int tx   = tid & 15;   // 0..15 -> col group of 8

    float acc[8][8];
#pragma unroll
    for (int i = 0; i < 8; i++)
#pragma unroll
        for (int j = 0; j < 8; j++) acc[i][j] = 0.f;

    for (int k0 = 0; k0 < 128; k0 += 32) {
        // A tile: 128 rows x 32 k (transposed into As[k][r])
#pragma unroll
        for (int i = 0; i < 16; i++) {
            int idx = tid + i * 256;           // 0..4095
            int r = idx >> 5, k = idx & 31;
            int gr = row0 + r;
            As[k][r] = (gr < n) ? A[(size_t)gr * 128 + k0 + k] : 0.f;
        }
        // B tile: 32 k x 128 cols
#pragma unroll
        for (int i = 0; i < 16; i++) {
            int idx = tid + i * 256;
            int k = idx >> 7, c = idx & 127;
            Bs[k][c] = W[(size_t)(k0 + k) * 128 + c];
        }
        __syncthreads();

#pragma unroll
        for (int k = 0; k < 32; k++) {
            float4 a0 = *(const float4*)&As[k][ty * 8];
            float4 a1 = *(const float4*)&As[k][ty * 8 + 4];
            float4 b0 = *(const float4*)&Bs[k][tx * 8];
            float4 b1 = *(const float4*)&Bs[k][tx * 8 + 4];
            float av[8] = {a0.x, a0.y, a0.z, a0.w, a1.x, a1.y, a1.z, a1.w};
            float bv[8] = {b0.x, b0.y, b0.z, b0.w, b1.x, b1.y, b1.z, b1.w};
#pragma unroll
            for (int i = 0; i < 8; i++)
#pragma unroll
                for (int j = 0; j < 8; j++)
                    acc[i][j] += av[i] * bv[j];
        }
        __syncthreads();
    }

    const int c_base = tx * 8;
    float bvals[8];
#pragma unroll
    for (int j = 0; j < 8; j++) bvals[j] = bias[c_base + j];

    if (EPI == 1) {
        float gv[8], bnv[8];
#pragma unroll
        for (int j = 0; j < 8; j++) { gv[j] = gam[c_base + j]; bnv[j] = bet[c_base + j]; }
#pragma unroll
        for (int i = 0; i < 8; i++) {
            float s = 0.f, q = 0.f;
#pragma unroll
            for (int j = 0; j < 8; j++) {
                float h = acc[i][j] + bvals[j];
                acc[i][j] = h;
                s += h; q += h * h;
            }
            // reduce across the 16 lanes (same ty) holding this row's 128 cols
#pragma unroll
            for (int o = 8; o >= 1; o >>= 1) {
                s += __shfl_xor_sync(0xffffffffu, s, o);
                q += __shfl_xor_sync(0xffffffffu, q, o);
            }
            float mean = s * (1.f / 128.f);
            float var  = q * (1.f / 128.f) - mean * mean;
            float rstd = rsqrtf(var + 1e-5f);
#pragma unroll
            for (int j = 0; j < 8; j++) {
                float v = (acc[i][j] - mean) * rstd * gv[j] + bnv[j];
                acc[i][j] = mish_f(v);
            }
        }
    } else {
#pragma unroll
        for (int i = 0; i < 8; i++)
#pragma unroll
            for (int j = 0; j < 8; j++)
                acc[i][j] += bvals[j];
    }

#pragma unroll
    for (int i = 0; i < 8; i++) {
        int gr = row0 + ty * 8 + i;
        if (gr >= n) continue;
        size_t base = (size_t)gr * 128 + c_base;
        if (EPI == 2) {
            float4 m0 = *(const float4*)&mul[base];
            float4 m1 = *(const float4*)&mul[base + 4];
            acc[i][0] *= m0.x; acc[i][1] *= m0.y; acc[i][2] *= m0.z; acc[i][3] *= m0.w;
            acc[i][4] *= m1.x; acc[i][5] *= m1.y; acc[i][6] *= m1.z; acc[i][7] *= m1.w;
        }
        float4 o0 = make_float4(acc[i][0], acc[i][1], acc[i][2], acc[i][3]);
        float4 o1 = make_float4(acc[i][4], acc[i][5], acc[i][6], acc[i][7]);
        *(float4*)&out[base]     = o0;
        *(float4*)&out[base + 4] = o1;
    }
}

// ---- per-segment, per-feature softmax (segments are contiguous; 128 feats = 128 threads) ----
__global__ void __launch_bounds__(128) seg_softmax_kernel(
    const float* __restrict__ in, float* __restrict__ out,
    const int* __restrict__ segstart)
{
    int b = blockIdx.x;
    int s = segstart[b], e = segstart[b + 1];
    int t = threadIdx.x;
    if (s >= e) return;
    float m = -3.4e38f;
    for (int r = s; r < e; r++) m = fmaxf(m, in[(size_t)r * 128 + t]);
    float d = 0.f;
    for (int r = s; r < e; r++) {
        float ev = __expf(in[(size_t)r * 128 + t] - m);
        d += ev;
        out[(size_t)r * 128 + t] = ev;
    }
    float inv = 1.f / d;
    for (int r = s; r < e; r++) out[(size_t)r * 128 + t] *= inv;
}

// ---- per-segment sum -> [NB,128] ----
__global__ void __launch_bounds__(128) seg_sum_kernel(
    const float* __restrict__ y, const int* __restrict__ segstart,
    float* __restrict__ out)
{
    int b = blockIdx.x;
    int s = segstart[b], e = segstart[b + 1];
    int t = threadIdx.x;
    float acc = 0.f;
    for (int r = s; r < e; r++) acc += y[(size_t)r * 128 + t];
    out[(size_t)b * 128 + t] = acc;
}

extern "C" void kernel_launch(void* const* d_in, const int* in_sizes, int n_in,
                              void* d_out, int out_size)
{
    const float* x     = (const float*)d_in[0];
    const int*   batch = (const int*)  d_in[1];
    // d_in[2] = n_batches scalar (fixed 4096)
    const float* W_map = (const float*)d_in[3];
    const float* b_map = (const float*)d_in[4];
    const float* kW1 = (const float*)d_in[5],  *kb1 = (const float*)d_in[6];
    const float* kg  = (const float*)d_in[7],  *kbn = (const float*)d_in[8];
    const float* kW2 = (const float*)d_in[9],  *kb2 = (const float*)d_in[10];
    const float* vW1 = (const float*)d_in[11], *vb1 = (const float*)d_in[12];
    const float* vg  = (const float*)d_in[13], *vbn = (const float*)d_in[14];
    const float* vW2 = (const float*)d_in[15], *vb2 = (const float*)d_in[16];
    const float* iW_map = (const float*)d_in[17], *ib_map = (const float*)d_in[18];
    const float* ikW1 = (const float*)d_in[19], *ikb1 = (const float*)d_in[20];
    const float* ikg  = (const float*)d_in[21], *ikbn = (const float*)d_in[22];
    const float* ikW2 = (const float*)d_in[23], *ikb2 = (const float*)d_in[24];
    const float* ivW1 = (const float*)d_in[25], *ivb1 = (const float*)d_in[26];
    const float* ivg  = (const float*)d_in[27], *ivbn = (const float*)d_in[28];
    const float* ivW2 = (const float*)d_in[29], *ivb2 = (const float*)d_in[30];

    int n = in_sizes[0] / 128;
    float* out = (float*)d_out;

    float *keys, *k2, *a, *v, *y; int* segstart;
    cudaGetSymbolAddress((void**)&keys, g_keys);
    cudaGetSymbolAddress((void**)&k2,   g_k2);
    cudaGetSymbolAddress((void**)&a,    g_a);
    cudaGetSymbolAddress((void**)&v,    g_v);
    cudaGetSymbolAddress((void**)&y,    g_y);
    cudaGetSymbolAddress((void**)&segstart, g_segstart);

    segstart_kernel<<<(NBATCH + 256) / 256, 256>>>(batch, n, segstart);

    int mb = (n + 127) / 128;

    // outer encoder
    gemm128<0><<<mb, 256>>>(x, W_map, b_map, nullptr, nullptr, nullptr, keys, n);
    seg_softmax_kernel<<<NBATCH, 128>>>(keys, keys, segstart);
    gemm128<1><<<mb, 256>>>(x,    vW1, vb1, vg, vbn, nullptr, a, n);
    gemm128<0><<<mb, 256>>>(a,    vW2, vb2, nullptr, nullptr, nullptr, v, n);
    gemm128<1><<<mb, 256>>>(keys, kW1, kb1, kg, kbn, nullptr, a, n);
    gemm128<2><<<mb, 256>>>(a,    kW2, kb2, nullptr, nullptr, v, y, n);
    seg_sum_kernel<<<NBATCH, 128>>>(y, segstart, out);

    // inner encoder on keys
    gemm128<0><<<mb, 256>>>(keys, iW_map, ib_map, nullptr, nullptr, nullptr, k2, n);
    seg_softmax_kernel<<<NBATCH, 128>>>(k2, k2, segstart);
    gemm128<1><<<mb, 256>>>(keys, ivW1, ivb1, ivg, ivbn, nullptr, a, n);
    gemm128<0><<<mb, 256>>>(a,    ivW2, ivb2, nullptr, nullptr, nullptr, v, n);
    gemm128<1><<<mb, 256>>>(k2,   ikW1, ikb1, ikg, ikbn, nullptr, a, n);
    gemm128<2><<<mb, 256>>>(a,    ikW2, ikb2, nullptr, nullptr, v, y, n);
    seg_sum_kernel<<<NBATCH, 128>>>(y, segstart, out + (size_t)NBATCH * 128);
}

// round 2
// speedup vs baseline: 1.5994x; 1.5994x over previous
#include <cuda_runtime.h>
#include <math.h>
#include <stdint.h>

#define MAXN   500000
#define NBATCH 4096

// ---- static scratch ----
__device__ __align__(16) float g_keys[(size_t)MAXN * 128];
__device__ __align__(16) float g_k2  [(size_t)MAXN * 128];
__device__ __align__(16) float g_a   [(size_t)MAXN * 128];
__device__ __align__(16) float g_v   [(size_t)MAXN * 128];
__device__ __align__(16) float g_y   [(size_t)MAXN * 128];
__device__ int g_segstart[NBATCH + 1];

__device__ __forceinline__ float mish_f(float x) {
    float sp = (x > 20.f) ? x : log1pf(__expf(x));
    return x * tanhf(sp);
}

__device__ __forceinline__ uint32_t f2tf(float f) {
    uint32_t u;
    asm("cvt.rna.tf32.f32 %0, %1;" : "=r"(u) : "f"(f));
    return u;
}

// ---- segment starts via binary search over sorted batch ----
__global__ void segstart_kernel(const int* __restrict__ batch, int n, int* __restrict__ segstart) {
    int b = blockIdx.x * blockDim.x + threadIdx.x;
    if (b > NBATCH) return;
    int lo = 0, hi = n;
    while (lo < hi) {
        int mid = (lo + hi) >> 1;
        if (batch[mid] < b) lo = mid + 1; else hi = mid;
    }
    segstart[b] = lo;
}

// ---- tf32 tensor-core GEMM: out[n,128] = A[n,128] @ W[128,128] (+epilogue) ----
// Block tile 128x128, 4 warps of 64x64 (4 m-tiles x 8 n-tiles each).
// EPI: 0 = bias, 1 = layernorm(g,bn)+mish, 2 = (acc+bias)*mul
template <int EPI>
__global__ void __launch_bounds__(128) gemm128_tc(
    const float* __restrict__ A, const float* __restrict__ W,
    const float* __restrict__ bias,
    const float* __restrict__ gam, const float* __restrict__ bet,
    const float* __restrict__ mul,
    float* __restrict__ out, int n)
{
    __shared__ uint32_t As[128][36];   // [row][k], pad-> bank = 4g+tig (conflict-free)
    __shared__ uint32_t Bs[32][136];   // [k][n],  pad-> bank = 8tig+n (conflict-free)
    __shared__ float s_sum[128][2];
    __shared__ float s_sq [128][2];

    const int tid  = threadIdx.x;
    const int lane = tid & 31;
    const int warp = tid >> 5;
    const int wm   = warp >> 1;      // 0..1 : M half
    const int wn   = warp & 1;       // 0..1 : N half
    const int g    = lane >> 2;      // groupID 0..7
    const int tig  = lane & 3;       // thread-in-group 0..3
    const int row0 = blockIdx.x * 128;

    float acc[4][8][4];
#pragma unroll
    for (int mt = 0; mt < 4; mt++)
#pragma unroll
        for (int j = 0; j < 8; j++)
#pragma unroll
            for (int c = 0; c < 4; c++) acc[mt][j][c] = 0.f;

    for (int k0 = 0; k0 < 128; k0 += 32) {
        // fill As: 128 rows x 32 k (tf32-converted)
#pragma unroll
        for (int i = 0; i < 8; i++) {
            int e = tid + i * 128;          // 0..1023
            int r = e >> 3, k4 = (e & 7) * 4;
            int gr = row0 + r;
            float4 v = (gr < n) ? *(const float4*)&A[(size_t)gr * 128 + k0 + k4]
                                : make_float4(0.f, 0.f, 0.f, 0.f);
            As[r][k4 + 0] = f2tf(v.x);
            As[r][k4 + 1] = f2tf(v.y);
            As[r][k4 + 2] = f2tf(v.z);
            As[r][k4 + 3] = f2tf(v.w);
        }
        // fill Bs: 32 k x 128 n
#pragma unroll
        for (int i = 0; i < 8; i++) {
            int e = tid + i * 128;
            int k = e >> 5, c4 = (e & 31) * 4;
            float4 v = *(const float4*)&W[(size_t)(k0 + k) * 128 + c4];
            Bs[k][c4 + 0] = f2tf(v.x);
            Bs[k][c4 + 1] = f2tf(v.y);
            Bs[k][c4 + 2] = f2tf(v.z);
            Bs[k][c4 + 3] = f2tf(v.w);
        }
        __syncthreads();

#pragma unroll
        for (int kk = 0; kk < 4; kk++) {
            const int kb = kk * 8;
            uint32_t af[4][4];
            uint32_t bf[8][2];
#pragma unroll
            for (int mt = 0; mt < 4; mt++) {
                int r = wm * 64 + mt * 16 + g;
                af[mt][0] = As[r    ][kb + tig];
                af[mt][1] = As[r + 8][kb + tig];
                af[mt][2] = As[r    ][kb + tig + 4];
                af[mt][3] = As[r + 8][kb + tig + 4];
            }
#pragma unroll
            for (int j = 0; j < 8; j++) {
                int nn = wn * 64 + j * 8 + g;
                bf[j][0] = Bs[kb + tig    ][nn];
                bf[j][1] = Bs[kb + tig + 4][nn];
            }
#pragma unroll
            for (int mt = 0; mt < 4; mt++)
#pragma unroll
                for (int j = 0; j < 8; j++)
                    asm volatile(
                        "mma.sync.aligned.m16n8k8.row.col.f32.tf32.tf32.f32 "
                        "{%0,%1,%2,%3}, {%4,%5,%6,%7}, {%8,%9}, {%0,%1,%2,%3};"
                        : "+f"(acc[mt][j][0]), "+f"(acc[mt][j][1]),
                          "+f"(acc[mt][j][2]), "+f"(acc[mt][j][3])
                        : "r"(af[mt][0]), "r"(af[mt][1]), "r"(af[mt][2]), "r"(af[mt][3]),
                          "r"(bf[j][0]), "r"(bf[j][1]));
        }
        __syncthreads();
    }

    // ---- fused epilogue ----
    // thread's cols: cb(j) = wn*64 + j*8 + 2*tig (+0/1)
    float2 bv[8];
#pragma unroll
    for (int j = 0; j < 8; j++)
        bv[j] = *(const float2*)&bias[wn * 64 + j * 8 + 2 * tig];

#pragma unroll
    for (int mt = 0; mt < 4; mt++)
#pragma unroll
        for (int j = 0; j < 8; j++) {
            acc[mt][j][0] += bv[j].x;
            acc[mt][j][1] += bv[j].y;
            acc[mt][j][2] += bv[j].x;
            acc[mt][j][3] += bv[j].y;
        }

    if (EPI == 1) {
        // per-row mean/var over 128 cols (64 here + 64 in the other wn warp)
#pragma unroll
        for (int mt = 0; mt < 4; mt++) {
            float s0 = 0.f, q0 = 0.f, s1 = 0.f, q1 = 0.f;
#pragma unroll
            for (int j = 0; j < 8; j++) {
                s0 += acc[mt][j][0] + acc[mt][j][1];
                q0 += acc[mt][j][0] * acc[mt][j][0] + acc[mt][j][1] * acc[mt][j][1];
                s1 += acc[mt][j][2] + acc[mt][j][3];
                q1 += acc[mt][j][2] * acc[mt][j][2] + acc[mt][j][3] * acc[mt][j][3];
            }
#pragma unroll
            for (int o = 1; o <= 2; o <<= 1) {
                s0 += __shfl_xor_sync(0xffffffffu, s0, o);
                q0 += __shfl_xor_sync(0xffffffffu, q0, o);
                s1 += __shfl_xor_sync(0xffffffffu, s1, o);
                q1 += __shfl_xor_sync(0xffffffffu, q1, o);
            }
            if (tig == 0) {
                int r = wm * 64 + mt * 16 + g;
                s_sum[r][wn] = s0; s_sq[r][wn] = q0;
                s_sum[r + 8][wn] = s1; s_sq[r + 8][wn] = q1;
            }
        }
        __syncthreads();

        float2 gv[8], bnv[8];
#pragma unroll
        for (int j = 0; j < 8; j++) {
            gv[j]  = *(const float2*)&gam[wn * 64 + j * 8 + 2 * tig];
            bnv[j] = *(const float2*)&bet[wn * 64 + j * 8 + 2 * tig];
        }
#pragma unroll
        for (int mt = 0; mt < 4; mt++) {
            int r0 = wm * 64 + mt * 16 + g;
            int r1 = r0 + 8;
            float mean0 = (s_sum[r0][0] + s_sum[r0][1]) * (1.f / 128.f);
            float var0  = (s_sq[r0][0]  + s_sq[r0][1])  * (1.f / 128.f) - mean0 * mean0;
            float rs0   = rsqrtf(var0 + 1e-5f);
            float mean1 = (s_sum[r1][0] + s_sum[r1][1]) * (1.f / 128.f);
            float var1  = (s_sq[r1][0]  + s_sq[r1][1])  * (1.f / 128.f) - mean1 * mean1;
            float rs1   = rsqrtf(var1 + 1e-5f);
#pragma unroll
            for (int j = 0; j < 8; j++) {
                acc[mt][j][0] = mish_f((acc[mt][j][0] - mean0) * rs0 * gv[j].x + bnv[j].x);
                acc[mt][j][1] = mish_f((acc[mt][j][1] - mean0) * rs0 * gv[j].y + bnv[j].y);
                acc[mt][j][2] = mish_f((acc[mt][j][2] - mean1) * rs1 * gv[j].x + bnv[j].x);
                acc[mt][j][3] = mish_f((acc[mt][j][3] - mean1) * rs1 * gv[j].y + bnv[j].y);
            }
        }
    }

    // ---- store (EPI==2 multiplies by mul) ----
#pragma unroll
    for (int mt = 0; mt < 4; mt++) {
        int r0 = row0 + wm * 64 + mt * 16 + g;
        int r1 = r0 + 8;
#pragma unroll
        for (int j = 0; j < 8; j++) {
            int cb = wn * 64 + j * 8 + 2 * tig;
            if (r0 < n) {
                size_t base = (size_t)r0 * 128 + cb;
                float ox = acc[mt][j][0], oy = acc[mt][j][1];
                if (EPI == 2) {
                    float2 m = *(const float2*)&mul[base];
                    ox *= m.x; oy *= m.y;
                }
                *(float2*)&out[base] = make_float2(ox, oy);
            }
            if (r1 < n) {
                size_t base = (size_t)r1 * 128 + cb;
                float ox = acc[mt][j][2], oy = acc[mt][j][3];
                if (EPI == 2) {
                    float2 m = *(const float2*)&mul[base];
                    ox *= m.x; oy *= m.y;
                }
                *(float2*)&out[base] = make_float2(ox, oy);
            }
        }
    }
}

// ---- per-segment, per-feature softmax (segments contiguous; 128 feats = 128 threads) ----
__global__ void __launch_bounds__(128) seg_softmax_kernel(
    const float* __restrict__ in, float* __restrict__ out,
    const int* __restrict__ segstart)
{
    int b = blockIdx.x;
    int s = segstart[b], e = segstart[b + 1];
    int t = threadIdx.x;
    if (s >= e) return;
    float m = -3.4e38f;
    for (int r = s; r < e; r++) m = fmaxf(m, in[(size_t)r * 128 + t]);
    float d = 0.f;
    for (int r = s; r < e; r++) {
        float ev = __expf(in[(size_t)r * 128 + t] - m);
        d += ev;
        out[(size_t)r * 128 + t] = ev;
    }
    float inv = 1.f / d;
    for (int r = s; r < e; r++) out[(size_t)r * 128 + t] *= inv;
}

// ---- per-segment sum -> [NB,128] ----
__global__ void __launch_bounds__(128) seg_sum_kernel(
    const float* __restrict__ y, const int* __restrict__ segstart,
    float* __restrict__ out)
{
    int b = blockIdx.x;
    int s = segstart[b], e = segstart[b + 1];
    int t = threadIdx.x;
    float acc = 0.f;
    for (int r = s; r < e; r++) acc += y[(size_t)r * 128 + t];
    out[(size_t)b * 128 + t] = acc;
}

extern "C" void kernel_launch(void* const* d_in, const int* in_sizes, int n_in,
                              void* d_out, int out_size)
{
    const float* x     = (const float*)d_in[0];
    const int*   batch = (const int*)  d_in[1];
    const float* W_map = (const float*)d_in[3];
    const float* b_map = (const float*)d_in[4];
    const float* kW1 = (const float*)d_in[5],  *kb1 = (const float*)d_in[6];
    const float* kg  = (const float*)d_in[7],  *kbn = (const float*)d_in[8];
    const float* kW2 = (const float*)d_in[9],  *kb2 = (const float*)d_in[10];
    const float* vW1 = (const float*)d_in[11], *vb1 = (const float*)d_in[12];
    const float* vg  = (const float*)d_in[13], *vbn = (const float*)d_in[14];
    const float* vW2 = (const float*)d_in[15], *vb2 = (const float*)d_in[16];
    const float* iW_map = (const float*)d_in[17], *ib_map = (const float*)d_in[18];
    const float* ikW1 = (const float*)d_in[19], *ikb1 = (const float*)d_in[20];
    const float* ikg  = (const float*)d_in[21], *ikbn = (const float*)d_in[22];
    const float* ikW2 = (const float*)d_in[23], *ikb2 = (const float*)d_in[24];
    const float* ivW1 = (const float*)d_in[25], *ivb1 = (const float*)d_in[26];
    const float* ivg  = (const float*)d_in[27], *ivbn = (const float*)d_in[28];
    const float* ivW2 = (const float*)d_in[29], *ivb2 = (const float*)d_in[30];

    int n = in_sizes[0] / 128;
    float* out = (float*)d_out;

    float *keys, *k2, *a, *v, *y; int* segstart;
    cudaGetSymbolAddress((void**)&keys, g_keys);
    cudaGetSymbolAddress((void**)&k2,   g_k2);
    cudaGetSymbolAddress((void**)&a,    g_a);
    cudaGetSymbolAddress((void**)&v,    g_v);
    cudaGetSymbolAddress((void**)&y,    g_y);
    cudaGetSymbolAddress((void**)&segstart, g_segstart);

    segstart_kernel<<<(NBATCH + 256) / 256, 256>>>(batch, n, segstart);

    int mb = (n + 127) / 128;

    // outer encoder
    gemm128_tc<0><<<mb, 128>>>(x, W_map, b_map, nullptr, nullptr, nullptr, keys, n);
    seg_softmax_kernel<<<NBATCH, 128>>>(keys, keys, segstart);
    gemm128_tc<1><<<mb, 128>>>(x,    vW1, vb1, vg, vbn, nullptr, a, n);
    gemm128_tc<0><<<mb, 128>>>(a,    vW2, vb2, nullptr, nullptr, nullptr, v, n);
    gemm128_tc<1><<<mb, 128>>>(keys, kW1, kb1, kg, kbn, nullptr, a, n);
    gemm128_tc<2><<<mb, 128>>>(a,    kW2, kb2, nullptr, nullptr, v, y, n);
    seg_sum_kernel<<<NBATCH, 128>>>(y, segstart, out);

    // inner encoder on keys
    gemm128_tc<0><<<mb, 128>>>(keys, iW_map, ib_map, nullptr, nullptr, nullptr, k2, n);
    seg_softmax_kernel<<<NBATCH, 128>>>(k2, k2, segstart);
    gemm128_tc<1><<<mb, 128>>>(keys, ivW1, ivb1, ivg, ivbn, nullptr, a, n);
    gemm128_tc<0><<<mb, 128>>>(a,    ivW2, ivb2, nullptr, nullptr, nullptr, v, n);
    gemm128_tc<1><<<mb, 128>>>(k2,   ikW1, ikb1, ikg, ikbn, nullptr, a, n);
    gemm128_tc<2><<<mb, 128>>>(a,    ikW2, ikb2, nullptr, nullptr, v, y, n);
    seg_sum_kernel<<<NBATCH, 128>>>(y, segstart, out + (size_t)NBATCH * 128);
}

// round 3
// speedup vs baseline: 1.7172x; 1.0737x over previous
#include <cuda_runtime.h>
#include <math.h>
#include <stdint.h>

#define MAXN   500000
#define NBATCH 4096

// ---- static scratch ----
__device__ __align__(16) float g_keys[(size_t)MAXN * 128];
__device__ __align__(16) float g_k2  [(size_t)MAXN * 128];
__device__ int g_segstart[NBATCH + 1];

struct SmemQ {
    uint32_t act[128][132];      // A operand / h1 (tf32), reused as y (float)
    uint32_t bs[2][32][136];     // double-buffered W chunk (tf32)
    float    ssum[128][4];
    float    ssq [128][4];
    int      sbatch[128];
};

__device__ __forceinline__ float mish_f(float x) {
    float sp = (x > 20.f) ? x : log1pf(__expf(x));
    return x * tanhf(sp);
}
__device__ __forceinline__ uint32_t f2tf(float f) {
    uint32_t u; asm("cvt.rna.tf32.f32 %0, %1;" : "=r"(u) : "f"(f)); return u;
}
__device__ __forceinline__ void mma8(float c[4], const uint32_t a[4], const uint32_t b[2]) {
    asm volatile("mma.sync.aligned.m16n8k8.row.col.f32.tf32.tf32.f32 "
        "{%0,%1,%2,%3},{%4,%5,%6,%7},{%8,%9},{%0,%1,%2,%3};"
        : "+f"(c[0]), "+f"(c[1]), "+f"(c[2]), "+f"(c[3])
        : "r"(a[0]), "r"(a[1]), "r"(a[2]), "r"(a[3]), "r"(b[0]), "r"(b[1]));
}

// ---- segment starts via binary search over sorted batch ----
__global__ void segstart_kernel(const int* __restrict__ batch, int n, int* __restrict__ segstart) {
    int b = blockIdx.x * blockDim.x + threadIdx.x;
    if (b > NBATCH) return;
    int lo = 0, hi = n;
    while (lo < hi) {
        int mid = (lo + hi) >> 1;
        if (batch[mid] < b) lo = mid + 1; else hi = mid;
    }
    segstart[b] = lo;
}

// ---- load a 128x128 fp32 tile -> smem act (tf32), zero-padded past n ----
__device__ __forceinline__ void fill_act(SmemQ* s, const float* __restrict__ src,
                                         int row0, int n, int tid) {
#pragma unroll
    for (int i = 0; i < 16; i++) {
        int e = tid + i * 256;
        int r = e >> 5, c4 = (e & 31) * 4;
        int gr = row0 + r;
        float4 v = make_float4(0.f, 0.f, 0.f, 0.f);
        if (gr < n) v = *(const float4*)(src + (size_t)gr * 128 + c4);
        s->act[r][c4 + 0] = f2tf(v.x);
        s->act[r][c4 + 1] = f2tf(v.y);
        s->act[r][c4 + 2] = f2tf(v.z);
        s->act[r][c4 + 3] = f2tf(v.w);
    }
}

// ---- GEMM: acc[128x128 block] = act(smem,tf32) @ W(gmem,streamed+prefetch) ----
// 8 warps, warp tile 64x32: rows wm*64+mt*16+g(+8), cols wn*32+j*8+2tig(+1)
__device__ __forceinline__ void gemm_act_W(SmemQ* s, const float* __restrict__ W,
                                           float acc[4][4][4],
                                           int wm, int wn, int g, int tig, int tid) {
    const int kw = tid >> 3, cw = (tid & 7) * 16;
#pragma unroll
    for (int mt = 0; mt < 4; mt++)
#pragma unroll
        for (int j = 0; j < 4; j++)
#pragma unroll
            for (int c = 0; c < 4; c++) acc[mt][j][c] = 0.f;

    float4 p[4];
#pragma unroll
    for (int u = 0; u < 4; u++) p[u] = *(const float4*)(W + (size_t)kw * 128 + cw + 4 * u);
#pragma unroll
    for (int u = 0; u < 4; u++) {
        s->bs[0][kw][cw + 4*u + 0] = f2tf(p[u].x);
        s->bs[0][kw][cw + 4*u + 1] = f2tf(p[u].y);
        s->bs[0][kw][cw + 4*u + 2] = f2tf(p[u].z);
        s->bs[0][kw][cw + 4*u + 3] = f2tf(p[u].w);
    }
    __syncthreads();

#pragma unroll
    for (int c = 0; c < 4; c++) {
        if (c < 3) {
#pragma unroll
            for (int u = 0; u < 4; u++)
                p[u] = *(const float4*)(W + (size_t)((c + 1) * 32 + kw) * 128 + cw + 4 * u);
        }
        const int buf = c & 1;
#pragma unroll
        for (int kk = 0; kk < 4; kk++) {
            const int ka = c * 32 + kk * 8, kb = kk * 8;
            uint32_t af[4][4], bf[4][2];
#pragma unroll
            for (int mt = 0; mt < 4; mt++) {
                int r = wm * 64 + mt * 16 + g;
                af[mt][0] = s->act[r][ka + tig];
                af[mt][1] = s->act[r + 8][ka + tig];
                af[mt][2] = s->act[r][ka + tig + 4];
                af[mt][3] = s->act[r + 8][ka + tig + 4];
            }
#pragma unroll
            for (int j = 0; j < 4; j++) {
                int nn = wn * 32 + j * 8 + g;
                bf[j][0] = s->bs[buf][kb + tig][nn];
                bf[j][1] = s->bs[buf][kb + tig + 4][nn];
            }
#pragma unroll
            for (int mt = 0; mt < 4; mt++)
#pragma unroll
                for (int j = 0; j < 4; j++) mma8(acc[mt][j], af[mt], bf[j]);
        }
        if (c < 3) {
            __syncthreads();
            const int nb = (c + 1) & 1;
#pragma unroll
            for (int u = 0; u < 4; u++) {
                s->bs[nb][kw][cw + 4*u + 0] = f2tf(p[u].x);
                s->bs[nb][kw][cw + 4*u + 1] = f2tf(p[u].y);
                s->bs[nb][kw][cw + 4*u + 2] = f2tf(p[u].z);
                s->bs[nb][kw][cw + 4*u + 3] = f2tf(p[u].w);
            }
            __syncthreads();
        }
    }
}

// ---- bias + layernorm + mish on acc, write result (tf32) back into act ----
__device__ __forceinline__ void ln_mish_act(SmemQ* s, float acc[4][4][4],
    const float* __restrict__ bias, const float* __restrict__ gam, const float* __restrict__ bet,
    int wm, int wn, int g, int tig)
{
    float2 bv[4], gv[4], bb[4];
#pragma unroll
    for (int j = 0; j < 4; j++) {
        int cc = wn * 32 + j * 8 + 2 * tig;
        bv[j] = *(const float2*)(bias + cc);
        gv[j] = *(const float2*)(gam + cc);
        bb[j] = *(const float2*)(bet + cc);
    }
#pragma unroll
    for (int mt = 0; mt < 4; mt++) {
        float s0 = 0.f, q0 = 0.f, s1 = 0.f, q1 = 0.f;
#pragma unroll
        for (int j = 0; j < 4; j++) {
            float a0 = acc[mt][j][0] + bv[j].x, a1 = acc[mt][j][1] + bv[j].y;
            float a2 = acc[mt][j][2] + bv[j].x, a3 = acc[mt][j][3] + bv[j].y;
            acc[mt][j][0] = a0; acc[mt][j][1] = a1; acc[mt][j][2] = a2; acc[mt][j][3] = a3;
            s0 += a0 + a1; q0 += a0 * a0 + a1 * a1;
            s1 += a2 + a3; q1 += a2 * a2 + a3 * a3;
        }
#pragma unroll
        for (int o = 1; o <= 2; o <<= 1) {
            s0 += __shfl_xor_sync(0xffffffffu, s0, o);
            q0 += __shfl_xor_sync(0xffffffffu, q0, o);
            s1 += __shfl_xor_sync(0xffffffffu, s1, o);
            q1 += __shfl_xor_sync(0xffffffffu, q1, o);
        }
        if (tig == 0) {
            int r = wm * 64 + mt * 16 + g;
            s->ssum[r][wn] = s0; s->ssq[r][wn] = q0;
            s->ssum[r + 8][wn] = s1; s->ssq[r + 8][wn] = q1;
        }
    }
    __syncthreads();   // also guarantees all warps finished reading act
#pragma unroll
    for (int mt = 0; mt < 4; mt++) {
        int r0 = wm * 64 + mt * 16 + g, r1 = r0 + 8;
        float su0 = s->ssum[r0][0] + s->ssum[r0][1] + s->ssum[r0][2] + s->ssum[r0][3];
        float sq0 = s->ssq [r0][0] + s->ssq [r0][1] + s->ssq [r0][2] + s->ssq [r0][3];
        float mean0 = su0 * (1.f / 128.f);
        float var0  = sq0 * (1.f / 128.f) - mean0 * mean0;
        float rs0   = rsqrtf(var0 + 1e-5f);
        float su1 = s->ssum[r1][0] + s->ssum[r1][1] + s->ssum[r1][2] + s->ssum[r1][3];
        float sq1 = s->ssq [r1][0] + s->ssq [r1][1] + s->ssq [r1][2] + s->ssq [r1][3];
        float mean1 = su1 * (1.f / 128.f);
        float var1  = sq1 * (1.f / 128.f) - mean1 * mean1;
        float rs1   = rsqrtf(var1 + 1e-5f);
#pragma unroll
        for (int j = 0; j < 4; j++) {
            int cc = wn * 32 + j * 8 + 2 * tig;
            float o0 = mish_f((acc[mt][j][0] - mean0) * rs0 * gv[j].x + bb[j].x);
            float o1 = mish_f((acc[mt][j][1] - mean0) * rs0 * gv[j].y + bb[j].y);
            float o2 = mish_f((acc[mt][j][2] - mean1) * rs1 * gv[j].x + bb[j].x);
            float o3 = mish_f((acc[mt][j][3] - mean1) * rs1 * gv[j].y + bb[j].y);
            s->act[r0][cc] = f2tf(o0); s->act[r0][cc + 1] = f2tf(o1);
            s->act[r1][cc] = f2tf(o2); s->act[r1][cc + 1] = f2tf(o3);
        }
    }
    __syncthreads();
}

// ---- mapping: out = A @ W + bias (fp32 out to gmem) ----
__global__ void __launch_bounds__(256, 1) map_kernel(
    const float* __restrict__ A, const float* __restrict__ W,
    const float* __restrict__ bias, float* __restrict__ out, int n)
{
    extern __shared__ char raw[];
    SmemQ* s = (SmemQ*)raw;
    const int tid = threadIdx.x, lane = tid & 31, warp = tid >> 5;
    const int wm = warp >> 2, wn = warp & 3, g = lane >> 2, tig = lane & 3;
    const int row0 = blockIdx.x * 128;

    fill_act(s, A, row0, n, tid);
    __syncthreads();
    float acc[4][4][4];
    gemm_act_W(s, W, acc, wm, wn, g, tig, tid);

    float2 bv[4];
#pragma unroll
    for (int j = 0; j < 4; j++) bv[j] = *(const float2*)(bias + wn * 32 + j * 8 + 2 * tig);
#pragma unroll
    for (int mt = 0; mt < 4; mt++) {
        int gr0 = row0 + wm * 64 + mt * 16 + g, gr1 = gr0 + 8;
#pragma unroll
        for (int j = 0; j < 4; j++) {
            int cc = wn * 32 + j * 8 + 2 * tig;
            if (gr0 < n)
                *(float2*)(out + (size_t)gr0 * 128 + cc) =
                    make_float2(acc[mt][j][0] + bv[j].x, acc[mt][j][1] + bv[j].y);
            if (gr1 < n)
                *(float2*)(out + (size_t)gr1 * 128 + cc) =
                    make_float2(acc[mt][j][2] + bv[j].x, acc[mt][j][3] + bv[j].y);
        }
    }
}

// ---- fused: segsum( mlp2(A1; a-params) * mlp2(A2; b-params) ) += out ----
__global__ void __launch_bounds__(256, 1) quad_kernel(
    const float* __restrict__ A1, const float* __restrict__ A2,
    const float* __restrict__ W1a, const float* __restrict__ b1a,
    const float* __restrict__ g1a, const float* __restrict__ n1a,
    const float* __restrict__ W2a, const float* __restrict__ b2a,
    const float* __restrict__ W1b, const float* __restrict__ b1b,
    const float* __restrict__ g1b, const float* __restrict__ n1b,
    const float* __restrict__ W2b, const float* __restrict__ b2b,
    const int* __restrict__ batch, float* __restrict__ out, int n)
{
    extern __shared__ char raw[];
    SmemQ* s = (SmemQ*)raw;
    const int tid = threadIdx.x, lane = tid & 31, warp = tid >> 5;
    const int wm = warp >> 2, wn = warp & 3, g = lane >> 2, tig = lane & 3;
    const int row0 = blockIdx.x * 128;

    if (tid < 128) s->sbatch[tid] = (row0 + tid < n) ? batch[row0 + tid] : -1;
    fill_act(s, A1, row0, n, tid);
    __syncthreads();

    float acc[4][4][4];
    // val side: h1v = LN/mish(A1@W1a + b1a); v = h1v@W2a + b2a  (kept in regs)
    gemm_act_W(s, W1a, acc, wm, wn, g, tig, tid);
    ln_mish_act(s, acc, b1a, g1a, n1a, wm, wn, g, tig);
    gemm_act_W(s, W2a, acc, wm, wn, g, tig, tid);

    float vv[4][4][4];
    {
        float2 b2[4];
#pragma unroll
        for (int j = 0; j < 4; j++) b2[j] = *(const float2*)(b2a + wn * 32 + j * 8 + 2 * tig);
#pragma unroll
        for (int mt = 0; mt < 4; mt++)
#pragma unroll
            for (int j = 0; j < 4; j++) {
                vv[mt][j][0] = acc[mt][j][0] + b2[j].x;
                vv[mt][j][1] = acc[mt][j][1] + b2[j].y;
                vv[mt][j][2] = acc[mt][j][2] + b2[j].x;
                vv[mt][j][3] = acc[mt][j][3] + b2[j].y;
            }
    }
    __syncthreads();                 // all warps done reading act (h1v)

    // key side: kq = mlp2(A2); y = kq * v
    fill_act(s, A2, row0, n, tid);
    __syncthreads();
    gemm_act_W(s, W1b, acc, wm, wn, g, tig, tid);
    ln_mish_act(s, acc, b1b, g1b, n1b, wm, wn, g, tig);
    gemm_act_W(s, W2b, acc, wm, wn, g, tig, tid);
    __syncthreads();                 // all warps done reading act (h1k)

    {
        float2 b2[4];
#pragma unroll
        for (int j = 0; j < 4; j++) b2[j] = *(const float2*)(b2b + wn * 32 + j * 8 + 2 * tig);
        float* Y = (float*)s->act;
#pragma unroll
        for (int mt = 0; mt < 4; mt++) {
            int r0 = wm * 64 + mt * 16 + g, r1 = r0 + 8;
#pragma unroll
            for (int j = 0; j < 4; j++) {
                int cc = wn * 32 + j * 8 + 2 * tig;
                Y[r0 * 132 + cc]     = (acc[mt][j][0] + b2[j].x) * vv[mt][j][0];
                Y[r0 * 132 + cc + 1] = (acc[mt][j][1] + b2[j].y) * vv[mt][j][1];
                Y[r1 * 132 + cc]     = (acc[mt][j][2] + b2[j].x) * vv[mt][j][2];
                Y[r1 * 132 + cc + 1] = (acc[mt][j][3] + b2[j].y) * vv[mt][j][3];
            }
        }
    }
    __syncthreads();

    // per-block run-length segment reduction + atomicAdd
    {
        const float* Y = (const float*)s->act;
        int c = tid & 127, q = tid >> 7;   // q in {0,1}: rows [64q, 64q+64)
        int r = q * 64;
        float a = 0.f;
        int cur = s->sbatch[r];
#pragma unroll 4
        for (int i = 0; i < 64; i++, r++) {
            int sb = s->sbatch[r];
            if (sb != cur) {
                if (cur >= 0) atomicAdd(out + (size_t)cur * 128 + c, a);
                a = 0.f; cur = sb;
            }
            a += Y[r * 132 + c];
        }
        if (cur >= 0) atomicAdd(out + (size_t)cur * 128 + c, a);
    }
}

// ---- per-segment, per-feature softmax, 2-pass online, in place ----
__global__ void __launch_bounds__(128) seg_softmax_kernel(
    float* __restrict__ io, const int* __restrict__ segstart)
{
    int b = blockIdx.x;
    int s0 = segstart[b], e = segstart[b + 1];
    int t = threadIdx.x;
    if (s0 >= e) return;
    float m = -3.4e38f, d = 0.f;
    for (int r = s0; r < e; r++) {
        float v = io[(size_t)r * 128 + t];
        float nm = fmaxf(m, v);
        d = d * __expf(m - nm) + __expf(v - nm);
        m = nm;
    }
    float inv = 1.f / d;
    for (int r = s0; r < e; r++) {
        float v = io[(size_t)r * 128 + t];
        io[(size_t)r * 128 + t] = __expf(v - m) * inv;
    }
}

extern "C" void kernel_launch(void* const* d_in, const int* in_sizes, int n_in,
                              void* d_out, int out_size)
{
    const float* x     = (const float*)d_in[0];
    const int*   batch = (const int*)  d_in[1];
    const float* W_map = (const float*)d_in[3];
    const float* b_map = (const float*)d_in[4];
    const float* kW1 = (const float*)d_in[5],  *kb1 = (const float*)d_in[6];
    const float* kg  = (const float*)d_in[7],  *kbn = (const float*)d_in[8];
    const float* kW2 = (const float*)d_in[9],  *kb2 = (const float*)d_in[10];
    const float* vW1 = (const float*)d_in[11], *vb1 = (const float*)d_in[12];
    const float* vg  = (const float*)d_in[13], *vbn = (const float*)d_in[14];
    const float* vW2 = (const float*)d_in[15], *vb2 = (const float*)d_in[16];
    const float* iW_map = (const float*)d_in[17], *ib_map = (const float*)d_in[18];
    const float* ikW1 = (const float*)d_in[19], *ikb1 = (const float*)d_in[20];
    const float* ikg  = (const float*)d_in[21], *ikbn = (const float*)d_in[22];
    const float* ikW2 = (const float*)d_in[23], *ikb2 = (const float*)d_in[24];
    const float* ivW1 = (const float*)d_in[25], *ivb1 = (const float*)d_in[26];
    const float* ivg  = (const float*)d_in[27], *ivbn = (const float*)d_in[28];
    const float* ivW2 = (const float*)d_in[29], *ivb2 = (const float*)d_in[30];

    int n = in_sizes[0] / 128;
    float* out = (float*)d_out;

    float *keys, *k2; int* segstart;
    cudaGetSymbolAddress((void**)&keys, g_keys);
    cudaGetSymbolAddress((void**)&k2,   g_k2);
    cudaGetSymbolAddress((void**)&segstart, g_segstart);

    const int SMB = (int)sizeof(SmemQ);
    cudaFuncSetAttribute(map_kernel,  cudaFuncAttributeMaxDynamicSharedMemorySize, SMB);
    cudaFuncSetAttribute(quad_kernel, cudaFuncAttributeMaxDynamicSharedMemorySize, SMB);

    cudaMemsetAsync(d_out, 0, (size_t)out_size * sizeof(float));
    segstart_kernel<<<(NBATCH + 256) / 256, 256>>>(batch, n, segstart);

    int mb = (n + 127) / 128;

    // outer encoder
    map_kernel<<<mb, 256, SMB>>>(x, W_map, b_map, keys, n);
    seg_softmax_kernel<<<NBATCH, 128>>>(keys, segstart);
    quad_kernel<<<mb, 256, SMB>>>(x, keys,
                                  vW1, vb1, vg, vbn, vW2, vb2,
                                  kW1, kb1, kg, kbn, kW2, kb2,
                                  batch, out, n);

    // inner encoder on keys
    map_kernel<<<mb, 256, SMB>>>(keys, iW_map, ib_map, k2, n);
    seg_softmax_kernel<<<NBATCH, 128>>>(k2, segstart);
    quad_kernel<<<mb, 256, SMB>>>(keys, k2,
                                  ivW1, ivb1, ivg, ivbn, ivW2, ivb2,
                                  ikW1, ikb1, ikg, ikbn, ikW2, ikb2,
                                  batch, out + (size_t)NBATCH * 128, n);
}

// round 5
// speedup vs baseline: 2.5051x; 1.4588x over previous
#include <cuda_runtime.h>
#include <math.h>
#include <stdint.h>

#define MAXN   500000
#define NBATCH 4096

// ---- static scratch ----
__device__ __align__(16) float g_keys[(size_t)MAXN * 128];
__device__ __align__(16) float g_k2  [(size_t)MAXN * 128];
__device__ int g_segstart[NBATCH + 1];

struct SmemQ {
    uint32_t act[128][132];      // operand tile (tf32); reused as y (float, stride 132)
    uint32_t bs[2][32][136];     // double-buffered W chunk (tf32)
    float    ssum[128][4];
    float    ssq [128][4];
    int      sbatch[128];
};

__device__ __forceinline__ float mish_f(float x) {
    float sp = (x > 20.f) ? x : log1pf(__expf(x));
    return x * tanhf(sp);
}
__device__ __forceinline__ uint32_t f2tf(float f) {
    uint32_t u; asm("cvt.rna.tf32.f32 %0, %1;" : "=r"(u) : "f"(f)); return u;
}
__device__ __forceinline__ void mma8(float c[4], const uint32_t a[4], const uint32_t b[2]) {
    asm volatile("mma.sync.aligned.m16n8k8.row.col.f32.tf32.tf32.f32 "
        "{%0,%1,%2,%3},{%4,%5,%6,%7},{%8,%9},{%0,%1,%2,%3};"
        : "+f"(c[0]), "+f"(c[1]), "+f"(c[2]), "+f"(c[3])
        : "r"(a[0]), "r"(a[1]), "r"(a[2]), "r"(a[3]), "r"(b[0]), "r"(b[1]));
}

// ---- segment starts via binary search over sorted batch ----
__global__ void segstart_kernel(const int* __restrict__ batch, int n, int* __restrict__ segstart) {
    int b = blockIdx.x * blockDim.x + threadIdx.x;
    if (b > NBATCH) return;
    int lo = 0, hi = n;
    while (lo < hi) { int m = (lo + hi) >> 1; if (batch[m] < b) lo = m + 1; else hi = m; }
    segstart[b] = lo;
}

// ---- load 128x128 fp32 tile -> smem act (tf32), zero-padded past n. 512 threads ----
__device__ __forceinline__ void fill_act(SmemQ* s, const float* __restrict__ src,
                                         int row0, int n, int tid) {
#pragma unroll
    for (int i = 0; i < 8; i++) {
        int e = tid + i * 512;
        int r = e >> 5, k4 = (e & 31) * 4;
        int gr = row0 + r;
        float4 v = make_float4(0.f, 0.f, 0.f, 0.f);
        if (gr < n) v = *(const float4*)(src + (size_t)gr * 128 + k4);
        s->act[r][k4 + 0] = f2tf(v.x);
        s->act[r][k4 + 1] = f2tf(v.y);
        s->act[r][k4 + 2] = f2tf(v.z);
        s->act[r][k4 + 3] = f2tf(v.w);
    }
}

// ---- GEMM: acc[128x128 block] = act(smem) @ W(gmem streamed, reg-prefetch double buffer)
// 16 warps, warp tile 32x32: rows wm*32+mt*16+g(+8), cols wn*32+j*8+2tig(+1)
__device__ __forceinline__ void gemm_act_W(SmemQ* s, const float* __restrict__ W,
                                           float acc[2][4][4],
                                           int wm, int wn, int g, int tig, int tid) {
    const int kw = tid >> 4, cw = (tid & 15) * 8;
#pragma unroll
    for (int mt = 0; mt < 2; mt++)
#pragma unroll
        for (int j = 0; j < 4; j++)
#pragma unroll
            for (int c = 0; c < 4; c++) acc[mt][j][c] = 0.f;

    float4 p0 = *(const float4*)(W + (size_t)kw * 128 + cw);
    float4 p1 = *(const float4*)(W + (size_t)kw * 128 + cw + 4);
    s->bs[0][kw][cw + 0] = f2tf(p0.x); s->bs[0][kw][cw + 1] = f2tf(p0.y);
    s->bs[0][kw][cw + 2] = f2tf(p0.z); s->bs[0][kw][cw + 3] = f2tf(p0.w);
    s->bs[0][kw][cw + 4] = f2tf(p1.x); s->bs[0][kw][cw + 5] = f2tf(p1.y);
    s->bs[0][kw][cw + 6] = f2tf(p1.z); s->bs[0][kw][cw + 7] = f2tf(p1.w);
    __syncthreads();

#pragma unroll
    for (int c = 0; c < 4; c++) {
        if (c < 3) {
            p0 = *(const float4*)(W + (size_t)((c + 1) * 32 + kw) * 128 + cw);
            p1 = *(const float4*)(W + (size_t)((c + 1) * 32 + kw) * 128 + cw + 4);
        }
        const int buf = c & 1;
#pragma unroll
        for (int kk = 0; kk < 4; kk++) {
            const int ka = c * 32 + kk * 8, kb = kk * 8;
            uint32_t af[2][4], bf[4][2];
#pragma unroll
            for (int mt = 0; mt < 2; mt++) {
                int r = wm * 32 + mt * 16 + g;
                af[mt][0] = s->act[r][ka + tig];
                af[mt][1] = s->act[r + 8][ka + tig];
                af[mt][2] = s->act[r][ka + tig + 4];
                af[mt][3] = s->act[r + 8][ka + tig + 4];
            }
#pragma unroll
            for (int j = 0; j < 4; j++) {
                int nn = wn * 32 + j * 8 + g;
                bf[j][0] = s->bs[buf][kb + tig][nn];
                bf[j][1] = s->bs[buf][kb + tig + 4][nn];
            }
#pragma unroll
            for (int mt = 0; mt < 2; mt++)
#pragma unroll
                for (int j = 0; j < 4; j++) mma8(acc[mt][j], af[mt], bf[j]);
        }
        if (c < 3) {
            __syncthreads();
            const int nb = (c + 1) & 1;
            s->bs[nb][kw][cw + 0] = f2tf(p0.x); s->bs[nb][kw][cw + 1] = f2tf(p0.y);
            s->bs[nb][kw][cw + 2] = f2tf(p0.z); s->bs[nb][kw][cw + 3] = f2tf(p0.w);
            s->bs[nb][kw][cw + 4] = f2tf(p1.x); s->bs[nb][kw][cw + 5] = f2tf(p1.y);
            s->bs[nb][kw][cw + 6] = f2tf(p1.z); s->bs[nb][kw][cw + 7] = f2tf(p1.w);
            __syncthreads();
        }
    }
}

// ---- bias + layernorm + mish on acc, write result (tf32) back into act ----
__device__ __forceinline__ void ln_mish_act(SmemQ* s, float acc[2][4][4],
    const float* __restrict__ bias, const float* __restrict__ gam, const float* __restrict__ bet,
    int wm, int wn, int g, int tig)
{
    float2 bv[4], gv[4], bb[4];
#pragma unroll
    for (int j = 0; j < 4; j++) {
        int cc = wn * 32 + j * 8 + 2 * tig;
        bv[j] = *(const float2*)(bias + cc);
        gv[j] = *(const float2*)(gam + cc);
        bb[j] = *(const float2*)(bet + cc);
    }
#pragma unroll
    for (int mt = 0; mt < 2; mt++) {
        float s0 = 0.f, q0 = 0.f, s1 = 0.f, q1 = 0.f;
#pragma unroll
        for (int j = 0; j < 4; j++) {
            float a0 = acc[mt][j][0] + bv[j].x, a1 = acc[mt][j][1] + bv[j].y;
            float a2 = acc[mt][j][2] + bv[j].x, a3 = acc[mt][j][3] + bv[j].y;
            acc[mt][j][0] = a0; acc[mt][j][1] = a1; acc[mt][j][2] = a2; acc[mt][j][3] = a3;
            s0 += a0 + a1; q0 += a0 * a0 + a1 * a1;
            s1 += a2 + a3; q1 += a2 * a2 + a3 * a3;
        }
#pragma unroll
        for (int o = 1; o <= 2; o <<= 1) {
            s0 += __shfl_xor_sync(0xffffffffu, s0, o);
            q0 += __shfl_xor_sync(0xffffffffu, q0, o);
            s1 += __shfl_xor_sync(0xffffffffu, s1, o);
            q1 += __shfl_xor_sync(0xffffffffu, q1, o);
        }
        if (tig == 0) {
            int r = wm * 32 + mt * 16 + g;
            s->ssum[r][wn] = s0; s->ssq[r][wn] = q0;
            s->ssum[r + 8][wn] = s1; s->ssq[r + 8][wn] = q1;
        }
    }
    __syncthreads();   // partials ready; also: all warps done reading act
#pragma unroll
    for (int mt = 0; mt < 2; mt++) {
        int r0 = wm * 32 + mt * 16 + g, r1 = r0 + 8;
        float su0 = s->ssum[r0][0] + s->ssum[r0][1] + s->ssum[r0][2] + s->ssum[r0][3];
        float sq0 = s->ssq [r0][0] + s->ssq [r0][1] + s->ssq [r0][2] + s->ssq [r0][3];
        float mean0 = su0 * (1.f / 128.f);
        float var0  = sq0 * (1.f / 128.f) - mean0 * mean0;
        float rs0   = rsqrtf(var0 + 1e-5f);
        float su1 = s->ssum[r1][0] + s->ssum[r1][1] + s->ssum[r1][2] + s->ssum[r1][3];
        float sq1 = s->ssq [r1][0] + s->ssq [r1][1] + s->ssq [r1][2] + s->ssq [r1][3];
        float mean1 = su1 * (1.f / 128.f);
        float var1  = sq1 * (1.f / 128.f) - mean1 * mean1;
        float rs1   = rsqrtf(var1 + 1e-5f);
#pragma unroll
        for (int j = 0; j < 4; j++) {
            int cc = wn * 32 + j * 8 + 2 * tig;
            float o0 = mish_f((acc[mt][j][0] - mean0) * rs0 * gv[j].x + bb[j].x);
            float o1 = mish_f((acc[mt][j][1] - mean0) * rs0 * gv[j].y + bb[j].y);
            float o2 = mish_f((acc[mt][j][2] - mean1) * rs1 * gv[j].x + bb[j].x);
            float o3 = mish_f((acc[mt][j][3] - mean1) * rs1 * gv[j].y + bb[j].y);
            s->act[r0][cc] = f2tf(o0); s->act[r0][cc + 1] = f2tf(o1);
            s->act[r1][cc] = f2tf(o2); s->act[r1][cc + 1] = f2tf(o3);
        }
    }
    __syncthreads();
}

// ---- mapping: out = A @ W + bias (fp32 to gmem) ----
__global__ void __launch_bounds__(512, 1) map_kernel(
    const float* __restrict__ A, const float* __restrict__ W,
    const float* __restrict__ bias, float* __restrict__ out, int n)
{
    extern __shared__ char raw[];
    SmemQ* s = (SmemQ*)raw;
    const int tid = threadIdx.x, lane = tid & 31, warp = tid >> 5;
    const int wm = warp >> 2, wn = warp & 3, g = lane >> 2, tig = lane & 3;
    const int row0 = blockIdx.x * 128;

    fill_act(s, A, row0, n, tid);
    float acc[2][4][4];
    gemm_act_W(s, W, acc, wm, wn, g, tig, tid);

    float2 bv[4];
#pragma unroll
    for (int j = 0; j < 4; j++) bv[j] = *(const float2*)(bias + wn * 32 + j * 8 + 2 * tig);
#pragma unroll
    for (int mt = 0; mt < 2; mt++) {
        int gr0 = row0 + wm * 32 + mt * 16 + g, gr1 = gr0 + 8;
#pragma unroll
        for (int j = 0; j < 4; j++) {
            int cc = wn * 32 + j * 8 + 2 * tig;
            if (gr0 < n)
                *(float2*)(out + (size_t)gr0 * 128 + cc) =
                    make_float2(acc[mt][j][0] + bv[j].x, acc[mt][j][1] + bv[j].y);
            if (gr1 < n)
                *(float2*)(out + (size_t)gr1 * 128 + cc) =
                    make_float2(acc[mt][j][2] + bv[j].x, acc[mt][j][3] + bv[j].y);
        }
    }
}

// ---- fused: segsum( mlp2(A1; a-params) * mlp2(A2; b-params) ) += out ----
__global__ void __launch_bounds__(512, 1) quad_kernel(
    const float* __restrict__ A1, const float* __restrict__ A2,
    const float* __restrict__ W1a, const float* __restrict__ b1a,
    const float* __restrict__ g1a, const float* __restrict__ n1a,
    const float* __restrict__ W2a, const float* __restrict__ b2a,
    const float* __restrict__ W1b, const float* __restrict__ b1b,
    const float* __restrict__ g1b, const float* __restrict__ n1b,
    const float* __restrict__ W2b, const float* __restrict__ b2b,
    const int* __restrict__ batch, float* __restrict__ out, int n)
{
    extern __shared__ char raw[];
    SmemQ* s = (SmemQ*)raw;
    const int tid = threadIdx.x, lane = tid & 31, warp = tid >> 5;
    const int wm = warp >> 2, wn = warp & 3, g = lane >> 2, tig = lane & 3;
    const int row0 = blockIdx.x * 128;

    if (tid < 128) s->sbatch[tid] = (row0 + tid < n) ? batch[row0 + tid] : -1;
    fill_act(s, A1, row0, n, tid);

    float acc[2][4][4];
    // val side: h1v = LN/mish(A1@W1a + b1a); v = h1v@W2a + b2a (in regs)
    gemm_act_W(s, W1a, acc, wm, wn, g, tig, tid);
    ln_mish_act(s, acc, b1a, g1a, n1a, wm, wn, g, tig);
    gemm_act_W(s, W2a, acc, wm, wn, g, tig, tid);

    float vv[2][4][4];
    {
        float2 b2[4];
#pragma unroll
        for (int j = 0; j < 4; j++) b2[j] = *(const float2*)(b2a + wn * 32 + j * 8 + 2 * tig);
#pragma unroll
        for (int mt = 0; mt < 2; mt++)
#pragma unroll
            for (int j = 0; j < 4; j++) {
                vv[mt][j][0] = acc[mt][j][0] + b2[j].x;
                vv[mt][j][1] = acc[mt][j][1] + b2[j].y;
                vv[mt][j][2] = acc[mt][j][2] + b2[j].x;
                vv[mt][j][3] = acc[mt][j][3] + b2[j].y;
            }
    }
    __syncthreads();                 // all warps done reading act (h1v)

    // key side: kq = mlp2(A2); y = kq * v
    fill_act(s, A2, row0, n, tid);
    gemm_act_W(s, W1b, acc, wm, wn, g, tig, tid);
    ln_mish_act(s, acc, b1b, g1b, n1b, wm, wn, g, tig);
    gemm_act_W(s, W2b, acc, wm, wn, g, tig, tid);
    __syncthreads();                 // all warps done reading act (h1k)

    {
        float2 b2[4];
#pragma unroll
        for (int j = 0; j < 4; j++) b2[j] = *(const float2*)(b2b + wn * 32 + j * 8 + 2 * tig);
        float* Y = (float*)s->act;
#pragma unroll
        for (int mt = 0; mt < 2; mt++) {
            int r0 = wm * 32 + mt * 16 + g, r1 = r0 + 8;
#pragma unroll
            for (int j = 0; j < 4; j++) {
                int cc = wn * 32 + j * 8 + 2 * tig;
                Y[r0 * 132 + cc]     = (acc[mt][j][0] + b2[j].x) * vv[mt][j][0];
                Y[r0 * 132 + cc + 1] = (acc[mt][j][1] + b2[j].y) * vv[mt][j][1];
                Y[r1 * 132 + cc]     = (acc[mt][j][2] + b2[j].x) * vv[mt][j][2];
                Y[r1 * 132 + cc + 1] = (acc[mt][j][3] + b2[j].y) * vv[mt][j][3];
            }
        }
    }
    __syncthreads();

    // per-block run-length segment reduction + atomicAdd (512 threads: 4 x 32-row strips)
    {
        const float* Y = (const float*)s->act;
        int c = tid & 127, qq = tid >> 7;   // qq in 0..3
        int r = qq * 32;
        float a = 0.f;
        int cur = s->sbatch[r];
#pragma unroll 4
        for (int i = 0; i < 32; i++, r++) {
            int sbv = s->sbatch[r];
            if (sbv != cur) {
                if (cur >= 0) atomicAdd(out + (size_t)cur * 128 + c, a);
                a = 0.f; cur = sbv;
            }
            a += Y[r * 132 + c];
        }
        if (cur >= 0) atomicAdd(out + (size_t)cur * 128 + c, a);
    }
}

// ---- per-segment, per-feature softmax, online, in place ----
__global__ void __launch_bounds__(128) seg_softmax_kernel(
    float* __restrict__ io, const int* __restrict__ segstart)
{
    int b = blockIdx.x;
    int s0 = segstart[b], e = segstart[b + 1];
    int t = threadIdx.x;
    if (s0 >= e) return;
    float m = -3.4e38f, d = 0.f;
    for (int r = s0; r < e; r++) {
        float v = io[(size_t)r * 128 + t];
        float nm = fmaxf(m, v);
        d = d * __expf(m - nm) + __expf(v - nm);
        m = nm;
    }
    float inv = 1.f / d;
    for (int r = s0; r < e; r++) {
        float v = io[(size_t)r * 128 + t];
        io[(size_t)r * 128 + t] = __expf(v - m) * inv;
    }
}

extern "C" void kernel_launch(void* const* d_in, const int* in_sizes, int n_in,
                              void* d_out, int out_size)
{
    const float* x     = (const float*)d_in[0];
    const int*   batch = (const int*)  d_in[1];
    const float* W_map = (const float*)d_in[3];
    const float* b_map = (const float*)d_in[4];
    const float* kW1 = (const float*)d_in[5],  *kb1 = (const float*)d_in[6];
    const float* kg  = (const float*)d_in[7],  *kbn = (const float*)d_in[8];
    const float* kW2 = (const float*)d_in[9],  *kb2 = (const float*)d_in[10];
    const float* vW1 = (const float*)d_in[11], *vb1 = (const float*)d_in[12];
    const float* vg  = (const float*)d_in[13], *vbn = (const float*)d_in[14];
    const float* vW2 = (const float*)d_in[15], *vb2 = (const float*)d_in[16];
    const float* iW_map = (const float*)d_in[17], *ib_map = (const float*)d_in[18];
    const float* ikW1 = (const float*)d_in[19], *ikb1 = (const float*)d_in[20];
    const float* ikg  = (const float*)d_in[21], *ikbn = (const float*)d_in[22];
    const float* ikW2 = (const float*)d_in[23], *ikb2 = (const float*)d_in[24];
    const float* ivW1 = (const float*)d_in[25], *ivb1 = (const float*)d_in[26];
    const float* ivg  = (const float*)d_in[27], *ivbn = (const float*)d_in[28];
    const float* ivW2 = (const float*)d_in[29], *ivb2 = (const float*)d_in[30];

    int n = in_sizes[0] / 128;
    float* out = (float*)d_out;

    float *keys, *k2; int* segstart;
    cudaGetSymbolAddress((void**)&keys, g_keys);
    cudaGetSymbolAddress((void**)&k2,   g_k2);
    cudaGetSymbolAddress((void**)&segstart, g_segstart);

    const int SMB = (int)sizeof(SmemQ);
    cudaFuncSetAttribute(map_kernel,  cudaFuncAttributeMaxDynamicSharedMemorySize, SMB);
    cudaFuncSetAttribute(quad_kernel, cudaFuncAttributeMaxDynamicSharedMemorySize, SMB);

    cudaMemsetAsync(d_out, 0, (size_t)out_size * sizeof(float));
    segstart_kernel<<<(NBATCH + 256) / 256, 256>>>(batch, n, segstart);

    int mb = (n + 127) / 128;

    // outer encoder
    map_kernel<<<mb, 512, SMB>>>(x, W_map, b_map, keys, n);
    seg_softmax_kernel<<<NBATCH, 128>>>(keys, segstart);
    quad_kernel<<<mb, 512, SMB>>>(x, keys,
                                  vW1, vb1, vg, vbn, vW2, vb2,
                                  kW1, kb1, kg, kbn, kW2, kb2,
                                  batch, out, n);

    // inner encoder on keys
    map_kernel<<<mb, 512, SMB>>>(keys, iW_map, ib_map, k2, n);
    seg_softmax_kernel<<<NBATCH, 128>>>(k2, segstart);
    quad_kernel<<<mb, 512, SMB>>>(keys, k2,
                                  ivW1, ivb1, ivg, ivbn, ivW2, ivb2,
                                  ikW1, ikb1, ikg, ikbn, ikW2, ikb2,
                                  batch, out + (size_t)NBATCH * 128, n);
}